// round 2
// baseline (speedup 1.0000x reference)
#include <cuda_runtime.h>
#include <math.h>

#define T_STEPS 20
#define NB 128          // batch
#define E_DIM 128       // embedding per step
#define C_DIM 512       // context dim
#define H_DIM 256       // hidden
#define V_DIM 32000     // vocab
#define G3 768          // live gates: i (0:256), g (256:512), o (512:768)
#define WIH_LD 640      // Wih row length (E+C)

// Scratch (no cudaMalloc allowed): ~21.7 MB total
__device__ float g_Cg[2 * NB * G3];                 // ctx gate part + biases, per stream
__device__ float g_G0[2 * T_STEPS * NB * G3];       // full input-gate precompute
__device__ float g_hs[2 * T_STEPS * NB * H_DIM];    // hidden states (also GEMM A)

__device__ __forceinline__ float sigm(float x) { return 1.0f / (1.0f + expf(-x)); }

// ---------------------------------------------------------------------------
// Small GEMM: C[m,n] = sum_k A[m,k] * W[wr(n), wcol0+k]   (64x64 tile, K%16==0)
// wr(n) = n + (n>=256 ? 256 : 0)  -- skips the dead f-gate rows of Wih.
// mode 0: C = g_Cg[s]   epilogue: + bih[wr] + bhh[wr]          (M=128, K=512)
// mode 1: C = g_G0[s]   epilogue: + g_Cg[s][m%128][n]          (M=2560, K=128)
// ---------------------------------------------------------------------------
__global__ __launch_bounds__(256) void gate_gemm64(
    const float* __restrict__ A0, const float* __restrict__ A1, int lda, int K,
    const float* __restrict__ W0, const float* __restrict__ W1, int wcol0,
    const float* __restrict__ b10, const float* __restrict__ b11,
    const float* __restrict__ b20, const float* __restrict__ b21,
    int mode)
{
    __shared__ float As[16][64];
    __shared__ float Ws[16][64];
    const int tid = threadIdx.x;
    const int tx = tid & 15, ty = tid >> 4;
    const int s  = blockIdx.z;
    const int m0 = blockIdx.y * 64;
    const int n0 = blockIdx.x * 64;
    const float* A = s ? A1 : A0;
    const float* W = s ? W1 : W0;

    const int lrow = tid >> 2;          // 0..63
    const int lkq  = (tid & 3) * 4;     // 0,4,8,12
    int wrow = n0 + lrow;
    if (wrow >= 256) wrow += 256;       // skip f-gate block
    const float* wptr = W + (size_t)wrow * WIH_LD + wcol0 + lkq;
    const float* aptr = A + (size_t)(m0 + lrow) * lda + lkq;

    float acc[4][4] = {};
    for (int k0 = 0; k0 < K; k0 += 16) {
        float4 av = *(const float4*)(aptr + k0);
        float4 wv = *(const float4*)(wptr + k0);
        As[lkq + 0][lrow] = av.x; As[lkq + 1][lrow] = av.y;
        As[lkq + 2][lrow] = av.z; As[lkq + 3][lrow] = av.w;
        Ws[lkq + 0][lrow] = wv.x; Ws[lkq + 1][lrow] = wv.y;
        Ws[lkq + 2][lrow] = wv.z; Ws[lkq + 3][lrow] = wv.w;
        __syncthreads();
#pragma unroll
        for (int kk = 0; kk < 16; kk++) {
            float a[4], b[4];
#pragma unroll
            for (int i = 0; i < 4; i++) a[i] = As[kk][ty * 4 + i];
#pragma unroll
            for (int j = 0; j < 4; j++) b[j] = Ws[kk][tx * 4 + j];
#pragma unroll
            for (int i = 0; i < 4; i++)
#pragma unroll
                for (int j = 0; j < 4; j++)
                    acc[i][j] = fmaf(a[i], b[j], acc[i][j]);
        }
        __syncthreads();
    }

    const float* bb1 = s ? b11 : b10;
    const float* bb2 = s ? b21 : b20;
#pragma unroll
    for (int i = 0; i < 4; i++) {
        const int m = m0 + ty * 4 + i;
#pragma unroll
        for (int j = 0; j < 4; j++) {
            const int n = n0 + tx * 4 + j;
            float v = acc[i][j];
            if (mode == 0) {
                int wr = n + (n >= 256 ? 256 : 0);
                v += bb1[wr] + bb2[wr];
                g_Cg[(size_t)s * NB * G3 + (size_t)m * G3 + n] = v;
            } else {
                v += g_Cg[(size_t)s * NB * G3 + (size_t)(m & (NB - 1)) * G3 + n];
                g_G0[(size_t)s * T_STEPS * NB * G3 + (size_t)m * G3 + n] = v;
            }
        }
    }
}

// ---------------------------------------------------------------------------
// One LSTM step (both streams). c-state is always zero (faithful to ref bug):
//   c_new = sigm(i)*tanh(g);  h = sigm(o)*tanh(c_new)
// CTA computes h tile [16 b x 32 c]; grid (8 c-tiles, 8 b-tiles, 2 streams)
// ---------------------------------------------------------------------------
__global__ __launch_bounds__(128) void lstm_step(
    int t,
    const float* __restrict__ Whh0, const float* __restrict__ Whh1,
    const float* __restrict__ h00,  const float* __restrict__ h01)
{
    __shared__ float As[16][16];      // hprev[k][b]
    __shared__ float Ws[3][16][32];   // Whh[gate][k][c]
    const int tid = threadIdx.x;
    const int tx = tid & 31, ty = tid >> 5;
    const int s  = blockIdx.z;
    const int c0 = blockIdx.x * 32;
    const int b0 = blockIdx.y * 16;
    const float* Whh = s ? Whh1 : Whh0;
    const float* h0v = s ? h01 : h00;
    const float* hprev = g_hs + (size_t)((s * T_STEPS + (t > 0 ? t - 1 : 0)) * NB) * H_DIM;

    float ai[4] = {}, ag[4] = {}, ao[4] = {};
    for (int k0 = 0; k0 < H_DIM; k0 += 16) {
#pragma unroll
        for (int i = 0; i < 2; i++) {
            int lin = tid + i * 128;
            int bb = lin >> 4, kk = lin & 15;
            float v = (t == 0) ? h0v[k0 + kk]
                               : hprev[(size_t)(b0 + bb) * H_DIM + k0 + kk];
            As[kk][bb] = v;
        }
#pragma unroll
        for (int i = 0; i < 12; i++) {
            int lin = tid + i * 128;
            int gi = lin >> 9;             // 0..2
            int rem = lin & 511;
            int cc = rem >> 4, kk = rem & 15;
            int gb = (gi + (gi ? 1 : 0)) << 8;   // 0, 512, 768 (skip f)
            Ws[gi][kk][cc] = Whh[(size_t)(gb + c0 + cc) * H_DIM + k0 + kk];
        }
        __syncthreads();
#pragma unroll
        for (int kk = 0; kk < 16; kk++) {
            float wi = Ws[0][kk][tx], wg = Ws[1][kk][tx], wo = Ws[2][kk][tx];
#pragma unroll
            for (int r = 0; r < 4; r++) {
                float a = As[kk][ty * 4 + r];
                ai[r] = fmaf(a, wi, ai[r]);
                ag[r] = fmaf(a, wg, ag[r]);
                ao[r] = fmaf(a, wo, ao[r]);
            }
        }
        __syncthreads();
    }
#pragma unroll
    for (int r = 0; r < 4; r++) {
        const int b = b0 + ty * 4 + r;
        const int c = c0 + tx;
        const size_t base = (size_t)((s * T_STEPS + t) * NB + b) * G3;
        float ip = ai[r] + g_G0[base + c];
        float gp = ag[r] + g_G0[base + 256 + c];
        float op = ao[r] + g_G0[base + 512 + c];
        float cn = sigm(ip) * tanhf(gp);
        float h  = sigm(op) * tanhf(cn);
        g_hs[(size_t)((s * T_STEPS + t) * NB + b) * H_DIM + c] = h;
    }
}

// ---------------------------------------------------------------------------
// Logits GEMM: out[m,v] = g_hs[m,:] . Wp[v,:] + bp[v]
// M=5120, N=32000, K=256. 128x128 CTA tile, 8x8 per thread (split 64-offset
// mapping so epilogue stores are coalesced float4s).
// ---------------------------------------------------------------------------
__global__ __launch_bounds__(256) void logits_gemm(
    const float* __restrict__ Wp, const float* __restrict__ bp,
    float* __restrict__ out)
{
    __shared__ float As[16][128];
    __shared__ float Ws[16][128];
    const int tid = threadIdx.x;
    const int tx = tid & 15, ty = tid >> 4;
    const int n0 = blockIdx.x * 128;
    const int m0 = blockIdx.y * 128;

    const int lrow = tid >> 1;          // 0..127
    const int lkq  = (tid & 1) * 8;     // 0 or 8
    const float* aptr = g_hs + (size_t)(m0 + lrow) * H_DIM + lkq;
    const float* wptr = Wp   + (size_t)(n0 + lrow) * H_DIM + lkq;

    float acc[8][8] = {};
    for (int k0 = 0; k0 < H_DIM; k0 += 16) {
        float4 a0 = *(const float4*)(aptr + k0);
        float4 a1 = *(const float4*)(aptr + k0 + 4);
        float4 w0 = *(const float4*)(wptr + k0);
        float4 w1 = *(const float4*)(wptr + k0 + 4);
        As[lkq + 0][lrow] = a0.x; As[lkq + 1][lrow] = a0.y;
        As[lkq + 2][lrow] = a0.z; As[lkq + 3][lrow] = a0.w;
        As[lkq + 4][lrow] = a1.x; As[lkq + 5][lrow] = a1.y;
        As[lkq + 6][lrow] = a1.z; As[lkq + 7][lrow] = a1.w;
        Ws[lkq + 0][lrow] = w0.x; Ws[lkq + 1][lrow] = w0.y;
        Ws[lkq + 2][lrow] = w0.z; Ws[lkq + 3][lrow] = w0.w;
        Ws[lkq + 4][lrow] = w1.x; Ws[lkq + 5][lrow] = w1.y;
        Ws[lkq + 6][lrow] = w1.z; Ws[lkq + 7][lrow] = w1.w;
        __syncthreads();
#pragma unroll
        for (int kk = 0; kk < 16; kk++) {
            float4 xa0 = *(const float4*)&As[kk][ty * 4];
            float4 xa1 = *(const float4*)&As[kk][64 + ty * 4];
            float4 xb0 = *(const float4*)&Ws[kk][tx * 4];
            float4 xb1 = *(const float4*)&Ws[kk][64 + tx * 4];
            float a[8] = {xa0.x, xa0.y, xa0.z, xa0.w, xa1.x, xa1.y, xa1.z, xa1.w};
            float b[8] = {xb0.x, xb0.y, xb0.z, xb0.w, xb1.x, xb1.y, xb1.z, xb1.w};
#pragma unroll
            for (int i = 0; i < 8; i++)
#pragma unroll
                for (int j = 0; j < 8; j++)
                    acc[i][j] = fmaf(a[i], b[j], acc[i][j]);
        }
        __syncthreads();
    }

    float4 bv0 = *(const float4*)&bp[n0 + tx * 4];
    float4 bv1 = *(const float4*)&bp[n0 + 64 + tx * 4];
    const float bb[8] = {bv0.x, bv0.y, bv0.z, bv0.w, bv1.x, bv1.y, bv1.z, bv1.w};
#pragma unroll
    for (int i = 0; i < 8; i++) {
        const int m = m0 + ((i < 4) ? (ty * 4 + i) : (64 + ty * 4 + (i - 4)));
        const int sIdx = m / (T_STEPS * NB);
        const int loc  = m - sIdx * (T_STEPS * NB);
        float* op = out + (size_t)sIdx * T_STEPS * NB * V_DIM + (size_t)loc * V_DIM + n0;
        float4 v0 = make_float4(acc[i][0] + bb[0], acc[i][1] + bb[1],
                                acc[i][2] + bb[2], acc[i][3] + bb[3]);
        float4 v1 = make_float4(acc[i][4] + bb[4], acc[i][5] + bb[5],
                                acc[i][6] + bb[6], acc[i][7] + bb[7]);
        *(float4*)(op + tx * 4)      = v0;
        *(float4*)(op + 64 + tx * 4) = v1;
    }
}

// ---------------------------------------------------------------------------
extern "C" void kernel_launch(void* const* d_in, const int* in_sizes, int n_in,
                              void* d_out, int out_size)
{
    const float* inputPrev = (const float*)d_in[0];
    const float* inputNext = (const float*)d_in[1];
    const float* context   = (const float*)d_in[2];
    const float* hidden1   = (const float*)d_in[3];
    const float* hidden2   = (const float*)d_in[4];
    const float* Wih_p     = (const float*)d_in[5];
    const float* Whh_p     = (const float*)d_in[6];
    const float* bih_p     = (const float*)d_in[7];
    const float* bhh_p     = (const float*)d_in[8];
    const float* Wih_n     = (const float*)d_in[9];
    const float* Whh_n     = (const float*)d_in[10];
    const float* bih_n     = (const float*)d_in[11];
    const float* bhh_n     = (const float*)d_in[12];
    const float* Wp        = (const float*)d_in[13];
    const float* bp        = (const float*)d_in[14];
    float* out = (float*)d_out;

    // 1) ctx-part of input gates + folded biases (t-invariant): g_Cg
    gate_gemm64<<<dim3(G3 / 64, NB / 64, 2), 256>>>(
        context, context, C_DIM, C_DIM,
        Wih_p, Wih_n, E_DIM,
        bih_p, bih_n, bhh_p, bhh_n, 0);

    // 2) per-t input part + g_Cg broadcast: g_G0
    gate_gemm64<<<dim3(G3 / 64, (T_STEPS * NB) / 64, 2), 256>>>(
        inputPrev, inputNext, E_DIM, E_DIM,
        Wih_p, Wih_n, 0,
        nullptr, nullptr, nullptr, nullptr, 1);

    // 3) recurrence: 20 sequential steps, both streams per launch
    for (int t = 0; t < T_STEPS; t++)
        lstm_step<<<dim3(H_DIM / 32, NB / 16, 2), 128>>>(
            t, Whh_p, Whh_n, hidden1, hidden2);

    // 4) logits projection (dominant GEMM)
    logits_gemm<<<dim3(V_DIM / 128, (2 * T_STEPS * NB) / 128), 256>>>(Wp, bp, out);
}